// round 1
// baseline (speedup 1.0000x reference)
#include <cuda_runtime.h>
#include <math.h>

#define D 64
#define MAX_E 1000000
#define MAX_N 100000

// ---- device scratch (no allocations allowed) ----
__device__ float g_score[MAX_E];        // raw score, then exp(score - max)
__device__ float g_sum[MAX_N];          // per-head softmax denominator
__device__ float g_agg[MAX_N * D];      // attention-weighted aggregation
__device__ float g_hA[MAX_N * D];       // ping-pong h buffers
__device__ float g_hB[MAX_N * D];
__device__ float g_max;                 // global score max

__device__ __forceinline__ void atomicMaxFloat(float* addr, float val) {
    if (!(val > -INFINITY)) return;     // skip -inf / nan contributions
    int* ia = (int*)addr;
    int old = *ia;
    while (__int_as_float(old) < val) {
        int assumed = old;
        old = atomicCAS(ia, assumed, __float_as_int(val));
        if (old == assumed) break;
    }
}

// ---- zero sum/agg, reset max ----
__global__ void k_init(int n_agg, int n_sum) {
    int i = blockIdx.x * blockDim.x + threadIdx.x;
    int stride = gridDim.x * blockDim.x;
    for (int j = i; j < n_agg; j += stride) g_agg[j] = 0.0f;
    for (int j = i; j < n_sum; j += stride) g_sum[j] = 0.0f;
    if (i == 0) g_max = -INFINITY;
}

// ---- copy entity_embed into output slab columns [0,64) ----
__global__ void k_copy0(const float* __restrict__ ent, float* __restrict__ out,
                        int N, int out_stride) {
    int i = blockIdx.x * blockDim.x + threadIdx.x;
    int total = N * D;
    if (i < total) {
        int n = i >> 6, j = i & 63;
        out[(size_t)n * out_stride + j] = ent[i];
    }
}

// ---- score pass: 4 threads per edge, float4 row loads ----
__global__ void k_score(const float* __restrict__ h,
                        const float* __restrict__ rel_emb,
                        const int* __restrict__ heads,
                        const int* __restrict__ rels,
                        const int* __restrict__ tails,
                        int E) {
    int tid = blockIdx.x * blockDim.x + threadIdx.x;
    int e = tid >> 2;
    int lane4 = tid & 3;
    float acc = -INFINITY;   // candidate for block max
    float sc = 0.0f;
    if (e < E) {
        int hi = heads[e], ti = tails[e], ri = rels[e];
        const float4* eh = (const float4*)(h + (size_t)hi * D) + lane4 * 4;
        const float4* et = (const float4*)(h + (size_t)ti * D) + lane4 * 4;
        const float4* er = (const float4*)(rel_emb + (size_t)ri * D) + lane4 * 4;
#pragma unroll
        for (int j = 0; j < 4; j++) {
            float4 a = eh[j], t = et[j], r = er[j];
            sc += t.x * tanhf(a.x + r.x);
            sc += t.y * tanhf(a.y + r.y);
            sc += t.z * tanhf(a.z + r.z);
            sc += t.w * tanhf(a.w + r.w);
        }
    }
    // reduce dot over the 4 lanes of this edge
    sc += __shfl_xor_sync(0xffffffffu, sc, 1);
    sc += __shfl_xor_sync(0xffffffffu, sc, 2);
    if (e < E && lane4 == 0) {
        g_score[e] = sc;
        acc = sc;
    }
    // block-level max -> single atomic
#pragma unroll
    for (int off = 16; off; off >>= 1)
        acc = fmaxf(acc, __shfl_xor_sync(0xffffffffu, acc, off));
    __shared__ float smax[8];
    if ((threadIdx.x & 31) == 0) smax[threadIdx.x >> 5] = acc;
    __syncthreads();
    if (threadIdx.x < 8) {
        float v = smax[threadIdx.x];
#pragma unroll
        for (int off = 4; off; off >>= 1)
            v = fmaxf(v, __shfl_xor_sync(0x000000ffu, v, off));
        if (threadIdx.x == 0) atomicMaxFloat(&g_max, v);
    }
}

// ---- exp + per-head denominator ----
__global__ void k_exp_sum(const int* __restrict__ heads, int E) {
    int e = blockIdx.x * blockDim.x + threadIdx.x;
    if (e >= E) return;
    float se = expf(g_score[e] - g_max);
    g_score[e] = se;
    atomicAdd(&g_sum[heads[e]], se);
}

// ---- attention-weighted scatter: 4 threads per edge ----
__global__ void k_agg(const float* __restrict__ h,
                      const int* __restrict__ heads,
                      const int* __restrict__ tails,
                      int E) {
    int tid = blockIdx.x * blockDim.x + threadIdx.x;
    int e = tid >> 2;
    if (e >= E) return;
    int lane4 = tid & 3;
    int hi = heads[e], ti = tails[e];
    float attn = g_score[e] / (g_sum[hi] + 1e-10f);
    const float4* et = (const float4*)(h + (size_t)ti * D) + lane4 * 4;
    float* dst = g_agg + (size_t)hi * D + lane4 * 16;
#pragma unroll
    for (int j = 0; j < 4; j++) {
        float4 t = et[j];
        atomicAdd(dst + 4 * j + 0, attn * t.x);
        atomicAdd(dst + 4 * j + 1, attn * t.y);
        atomicAdd(dst + 4 * j + 2, attn * t.z);
        atomicAdd(dst + 4 * j + 3, attn * t.w);
    }
}

// ---- (h + agg) @ W.T, leaky_relu; write h_next and output slab ----
__global__ void k_linear(const float* __restrict__ h,
                         const float* __restrict__ W,
                         float* __restrict__ hnext,
                         float* __restrict__ out,
                         int N, int out_stride, int col_off) {
    __shared__ float Wsh[D * 65];      // Wsh[k*65 + j] = W[j*D + k]
    __shared__ float xs[4][D];
    for (int idx = threadIdx.x; idx < D * D; idx += blockDim.x) {
        int jj = idx >> 6, kk = idx & 63;
        Wsh[kk * 65 + jj] = W[idx];
    }
    __syncthreads();

    int j = threadIdx.x & 63;
    int slot = threadIdx.x >> 6;       // 0..3 (256 threads)
    for (int base = blockIdx.x * 4; base < N; base += gridDim.x * 4) {
        int n = base + slot;
        if (n < N)
            xs[slot][j] = h[(size_t)n * D + j] + g_agg[(size_t)n * D + j];
        __syncthreads();
        if (n < N) {
            float acc = 0.0f;
#pragma unroll
            for (int k = 0; k < D; k++)
                acc = fmaf(xs[slot][k], Wsh[k * 65 + j], acc);
            float r = acc > 0.0f ? acc : 0.2f * acc;
            hnext[(size_t)n * D + j] = r;
            out[(size_t)n * out_stride + col_off + j] = r;
        }
        __syncthreads();
    }
}

extern "C" void kernel_launch(void* const* d_in, const int* in_sizes, int n_in,
                              void* d_out, int out_size) {
    const int*   heads      = (const int*)d_in[0];
    const int*   rels       = (const int*)d_in[1];
    const int*   tails      = (const int*)d_in[2];
    const float* ent        = (const float*)d_in[3];
    const float* rel_embeds = (const float*)d_in[4];
    const float* Ws         = (const float*)d_in[5];
    float*       out        = (float*)d_out;

    int E = in_sizes[0];
    int N = in_sizes[3] / D;
    int L = in_sizes[5] / (D * D);
    int NREL = (L > 0) ? in_sizes[4] / (L * D) : 0;
    int out_stride = D * (L + 1);

    // layer-0 columns of the output
    k_copy0<<<(N * D + 255) / 256, 256>>>(ent, out, N, out_stride);

    float *hA, *hB;
    cudaGetSymbolAddress((void**)&hA, g_hA);
    cudaGetSymbolAddress((void**)&hB, g_hB);
    float* hbufs[2] = {hA, hB};

    const float* hcur = ent;
    int eblocks4 = (E * 4 + 255) / 256;
    int eblocks1 = (E + 255) / 256;

    for (int l = 0; l < L; l++) {
        k_init<<<2048, 256>>>(N * D, N);
        k_score<<<eblocks4, 256>>>(hcur, rel_embeds + (size_t)l * NREL * D,
                                   heads, rels, tails, E);
        k_exp_sum<<<eblocks1, 256>>>(heads, E);
        k_agg<<<eblocks4, 256>>>(hcur, heads, tails, E);
        float* hnext = hbufs[l & 1];
        k_linear<<<2048, 256>>>(hcur, Ws + (size_t)l * D * D, hnext, out,
                                N, out_stride, (l + 1) * D);
        hcur = hnext;
    }
}

// round 2
// speedup vs baseline: 1.6867x; 1.6867x over previous
#include <cuda_runtime.h>
#include <math.h>

#define D 64
#define MAX_E 1000000
#define MAX_N 100000

// ---- device scratch (no allocations allowed) ----
__device__ __align__(16) float g_sum[MAX_N];          // per-head Σ exp(score)
__device__ __align__(16) float g_agg[MAX_N * D];      // Σ exp(score) * e_t (unnormalized)
__device__ __align__(16) float g_hA[MAX_N * D];       // ping-pong h buffers
__device__ __align__(16) float g_hB[MAX_N * D];

__device__ __forceinline__ float tanh_fast(float x) {
    // tanh(x) = (e^{2x}-1)/(e^{2x}+1), e^{2x} = 2^{2x*log2(e)}
    float t, r;
    asm("ex2.approx.f32 %0, %1;" : "=f"(t) : "f"(x * 2.885390081777927f));
    asm("rcp.approx.f32 %0, %1;" : "=f"(r) : "f"(t + 1.0f));
    return (t - 1.0f) * r;
}

__device__ __forceinline__ float exp_fast(float x) {
    float t;
    asm("ex2.approx.f32 %0, %1;" : "=f"(t) : "f"(x * 1.4426950408889634f));
    return t;
}

__device__ __forceinline__ void red_add_v4(float* addr, float a, float b, float c, float d) {
    asm volatile("red.global.add.v4.f32 [%0], {%1, %2, %3, %4};"
                 :: "l"(addr), "f"(a), "f"(b), "f"(c), "f"(d) : "memory");
}

// ---- zero agg + sum ----
__global__ void k_init(int n4_agg, int n_sum) {
    int i = blockIdx.x * blockDim.x + threadIdx.x;
    int stride = gridDim.x * blockDim.x;
    float4 z = {0.f, 0.f, 0.f, 0.f};
    float4* agg4 = (float4*)g_agg;
    for (int j = i; j < n4_agg; j += stride) agg4[j] = z;
    for (int j = i; j < n_sum; j += stride) g_sum[j] = 0.0f;
}

// ---- copy entity_embed into output slab columns [0,64) ----
__global__ void k_copy0(const float* __restrict__ ent, float* __restrict__ out,
                        int N, int out_stride) {
    int i = blockIdx.x * blockDim.x + threadIdx.x;
    int total = N * (D / 4);
    if (i < total) {
        int n = i >> 4, f = i & 15;
        float4 v = ((const float4*)ent)[i];
        *(float4*)(out + (size_t)n * out_stride + f * 4) = v;
    }
}

// ---- fused edge pass: score -> exp -> scatter exp & exp*e_t. 4 threads/edge. ----
__global__ void __launch_bounds__(256) k_edge(
        const float* __restrict__ h,
        const float* __restrict__ rel_emb,
        const int* __restrict__ heads,
        const int* __restrict__ rels,
        const int* __restrict__ tails,
        int E) {
    int tid = blockIdx.x * blockDim.x + threadIdx.x;
    int e = tid >> 2;
    if (e >= E) return;
    int l4 = tid & 3;
    int hi = __ldg(heads + e), ti = __ldg(tails + e), ri = __ldg(rels + e);

    const float4* ph = (const float4*)(h + (size_t)hi * D) + l4 * 4;
    const float4* pt = (const float4*)(h + (size_t)ti * D) + l4 * 4;
    const float4* pr = (const float4*)(rel_emb + (size_t)ri * D) + l4 * 4;

    float4 a0 = ph[0], a1 = ph[1], a2 = ph[2], a3 = ph[3];
    float4 t0 = pt[0], t1 = pt[1], t2 = pt[2], t3 = pt[3];
    float4 r0 = pr[0], r1 = pr[1], r2 = pr[2], r3 = pr[3];

    float sc = 0.0f;
    sc += t0.x * tanh_fast(a0.x + r0.x);
    sc += t0.y * tanh_fast(a0.y + r0.y);
    sc += t0.z * tanh_fast(a0.z + r0.z);
    sc += t0.w * tanh_fast(a0.w + r0.w);
    sc += t1.x * tanh_fast(a1.x + r1.x);
    sc += t1.y * tanh_fast(a1.y + r1.y);
    sc += t1.z * tanh_fast(a1.z + r1.z);
    sc += t1.w * tanh_fast(a1.w + r1.w);
    sc += t2.x * tanh_fast(a2.x + r2.x);
    sc += t2.y * tanh_fast(a2.y + r2.y);
    sc += t2.z * tanh_fast(a2.z + r2.z);
    sc += t2.w * tanh_fast(a2.w + r2.w);
    sc += t3.x * tanh_fast(a3.x + r3.x);
    sc += t3.y * tanh_fast(a3.y + r3.y);
    sc += t3.z * tanh_fast(a3.z + r3.z);
    sc += t3.w * tanh_fast(a3.w + r3.w);

    // reduce dot over the 4 lanes of this edge
    sc += __shfl_xor_sync(0xffffffffu, sc, 1);
    sc += __shfl_xor_sync(0xffffffffu, sc, 2);

    float ex = exp_fast(sc);   // unnormalized softmax weight (global shift cancels)

    float* dst = g_agg + (size_t)hi * D + l4 * 16;
    red_add_v4(dst +  0, ex * t0.x, ex * t0.y, ex * t0.z, ex * t0.w);
    red_add_v4(dst +  4, ex * t1.x, ex * t1.y, ex * t1.z, ex * t1.w);
    red_add_v4(dst +  8, ex * t2.x, ex * t2.y, ex * t2.z, ex * t2.w);
    red_add_v4(dst + 12, ex * t3.x, ex * t3.y, ex * t3.z, ex * t3.w);
    if (l4 == 0) atomicAdd(&g_sum[hi], ex);
}

// ---- x = h + agg/(sum+eps); out = leaky(x @ W.T); write hnext + output slab ----
__global__ void __launch_bounds__(256) k_linear(
        const float* __restrict__ h,
        const float* __restrict__ W,
        float* __restrict__ hnext,
        float* __restrict__ out,
        int N, int out_stride, int col_off) {
    __shared__ float Wsh[D * D];       // Wsh[k*64 + j] = W[j*64 + k]
    __shared__ float xs[16][D + 1];
    for (int idx = threadIdx.x; idx < D * D; idx += blockDim.x) {
        int jj = idx >> 6, kk = idx & 63;
        Wsh[kk * D + jj] = W[idx];
    }
    __syncthreads();

    int s  = threadIdx.x >> 4;          // node slot 0..15
    int j4 = (threadIdx.x & 15) * 4;    // output column group

    for (int base = blockIdx.x * 16; base < N; base += gridDim.x * 16) {
        // cooperative load: 16 nodes x 64 floats, one float4 per thread
        int node = base + (threadIdx.x >> 4);
        int f4   = (threadIdx.x & 15) * 4;
        if (node < N) {
            float inv = 1.0f / (g_sum[node] + 1e-10f);
            float4 hv = *(const float4*)(h + (size_t)node * D + f4);
            float4 av = *(const float4*)(g_agg + (size_t)node * D + f4);
            float* row = xs[threadIdx.x >> 4];
            row[f4 + 0] = hv.x + av.x * inv;
            row[f4 + 1] = hv.y + av.y * inv;
            row[f4 + 2] = hv.z + av.z * inv;
            row[f4 + 3] = hv.w + av.w * inv;
        }
        __syncthreads();

        int n = base + s;
        if (n < N) {
            float ax = 0.f, ay = 0.f, az = 0.f, aw = 0.f;
            const float* xr = xs[s];
#pragma unroll
            for (int k = 0; k < D; k++) {
                float xv = xr[k];
                float4 w = *(const float4*)(Wsh + k * D + j4);
                ax = fmaf(xv, w.x, ax);
                ay = fmaf(xv, w.y, ay);
                az = fmaf(xv, w.z, az);
                aw = fmaf(xv, w.w, aw);
            }
            float4 r;
            r.x = ax > 0.f ? ax : 0.2f * ax;
            r.y = ay > 0.f ? ay : 0.2f * ay;
            r.z = az > 0.f ? az : 0.2f * az;
            r.w = aw > 0.f ? aw : 0.2f * aw;
            *(float4*)(hnext + (size_t)n * D + j4) = r;
            *(float4*)(out + (size_t)n * out_stride + col_off + j4) = r;
        }
        __syncthreads();
    }
}

extern "C" void kernel_launch(void* const* d_in, const int* in_sizes, int n_in,
                              void* d_out, int out_size) {
    const int*   heads      = (const int*)d_in[0];
    const int*   rels       = (const int*)d_in[1];
    const int*   tails      = (const int*)d_in[2];
    const float* ent        = (const float*)d_in[3];
    const float* rel_embeds = (const float*)d_in[4];
    const float* Ws         = (const float*)d_in[5];
    float*       out        = (float*)d_out;

    int E = in_sizes[0];
    int N = in_sizes[3] / D;
    int L = in_sizes[5] / (D * D);
    int NREL = (L > 0) ? in_sizes[4] / (L * D) : 0;
    int out_stride = D * (L + 1);

    k_copy0<<<(N * (D / 4) + 255) / 256, 256>>>(ent, out, N, out_stride);

    float *hA, *hB;
    cudaGetSymbolAddress((void**)&hA, g_hA);
    cudaGetSymbolAddress((void**)&hB, g_hB);
    float* hbufs[2] = {hA, hB};

    const float* hcur = ent;
    int eblocks = (E * 4 + 255) / 256;
    int lblocks = (N + 15) / 16;

    for (int l = 0; l < L; l++) {
        k_init<<<1024, 256>>>(N * D / 4, N);
        k_edge<<<eblocks, 256>>>(hcur, rel_embeds + (size_t)l * NREL * D,
                                 heads, rels, tails, E);
        float* hnext = hbufs[l & 1];
        k_linear<<<lblocks, 256>>>(hcur, Ws + (size_t)l * D * D, hnext, out,
                                   N, out_stride, (l + 1) * D);
        hcur = hnext;
    }
}

// round 3
// speedup vs baseline: 2.8788x; 1.7068x over previous
#include <cuda_runtime.h>
#include <math.h>

#define D 64
#define MAX_E 1000000
#define MAX_N 100000

// ---- device scratch (no allocations allowed) ----
__device__ __align__(16) float g_sum[MAX_N];          // per-head Σ exp(score)
__device__ __align__(16) float g_agg[MAX_N * D];      // Σ exp(score) * e_t (unnormalized)

__device__ __forceinline__ float tanh_fast(float x) {
    float t, r;
    asm("ex2.approx.f32 %0, %1;" : "=f"(t) : "f"(x * 2.885390081777927f));
    asm("rcp.approx.f32 %0, %1;" : "=f"(r) : "f"(t + 1.0f));
    return (t - 1.0f) * r;
}

__device__ __forceinline__ float exp_fast(float x) {
    float t;
    asm("ex2.approx.f32 %0, %1;" : "=f"(t) : "f"(x * 1.4426950408889634f));
    return t;
}

__device__ __forceinline__ void red_add_v4(float* addr, float a, float b, float c, float d) {
    asm volatile("red.global.add.v4.f32 [%0], {%1, %2, %3, %4};"
                 :: "l"(addr), "f"(a), "f"(b), "f"(c), "f"(d) : "memory");
}

// ---- zero agg + sum (once, before layer 0) ----
__global__ void k_init(int n4_agg, int n_sum) {
    int i = blockIdx.x * blockDim.x + threadIdx.x;
    int stride = gridDim.x * blockDim.x;
    float4 z = {0.f, 0.f, 0.f, 0.f};
    float4* agg4 = (float4*)g_agg;
    for (int j = i; j < n4_agg; j += stride) agg4[j] = z;
    for (int j = i; j < n_sum; j += stride) g_sum[j] = 0.0f;
}

// ---- copy entity_embed into output slab columns [0,64) ----
__global__ void k_copy0(const float* __restrict__ ent, float* __restrict__ out,
                        int N, int out_stride) {
    int i = blockIdx.x * blockDim.x + threadIdx.x;
    int total = N * (D / 4);
    if (i < total) {
        int n = i >> 4, f = i & 15;
        float4 v = ((const float4*)ent)[i];
        *(float4*)(out + (size_t)n * out_stride + f * 4) = v;
    }
}

// ---- fused edge pass: score -> exp -> scatter exp & exp*e_t. 4 threads/edge. ----
// h rows live at h + node*h_stride (stride in floats; row itself is 64 floats).
__global__ void __launch_bounds__(256) k_edge(
        const float* __restrict__ h, int h_stride,
        const float* __restrict__ rel_emb,
        const int* __restrict__ heads,
        const int* __restrict__ rels,
        const int* __restrict__ tails,
        int E) {
    int tid = blockIdx.x * blockDim.x + threadIdx.x;
    int e = tid >> 2;
    if (e >= E) return;
    int l4 = tid & 3;
    int hi = __ldg(heads + e), ti = __ldg(tails + e), ri = __ldg(rels + e);

    const float4* ph = (const float4*)(h + (size_t)hi * h_stride) + l4 * 4;
    const float4* pt = (const float4*)(h + (size_t)ti * h_stride) + l4 * 4;
    const float4* pr = (const float4*)(rel_emb + (size_t)ri * D) + l4 * 4;

    float4 a0 = ph[0], a1 = ph[1], a2 = ph[2], a3 = ph[3];
    float4 t0 = pt[0], t1 = pt[1], t2 = pt[2], t3 = pt[3];
    float4 r0 = pr[0], r1 = pr[1], r2 = pr[2], r3 = pr[3];

    float sc = 0.0f;
    sc += t0.x * tanh_fast(a0.x + r0.x);
    sc += t0.y * tanh_fast(a0.y + r0.y);
    sc += t0.z * tanh_fast(a0.z + r0.z);
    sc += t0.w * tanh_fast(a0.w + r0.w);
    sc += t1.x * tanh_fast(a1.x + r1.x);
    sc += t1.y * tanh_fast(a1.y + r1.y);
    sc += t1.z * tanh_fast(a1.z + r1.z);
    sc += t1.w * tanh_fast(a1.w + r1.w);
    sc += t2.x * tanh_fast(a2.x + r2.x);
    sc += t2.y * tanh_fast(a2.y + r2.y);
    sc += t2.z * tanh_fast(a2.z + r2.z);
    sc += t2.w * tanh_fast(a2.w + r2.w);
    sc += t3.x * tanh_fast(a3.x + r3.x);
    sc += t3.y * tanh_fast(a3.y + r3.y);
    sc += t3.z * tanh_fast(a3.z + r3.z);
    sc += t3.w * tanh_fast(a3.w + r3.w);

    sc += __shfl_xor_sync(0xffffffffu, sc, 1);
    sc += __shfl_xor_sync(0xffffffffu, sc, 2);

    float ex = exp_fast(sc);   // unnormalized weight (global max shift cancels)

    float* dst = g_agg + (size_t)hi * D + l4 * 16;
    red_add_v4(dst +  0, ex * t0.x, ex * t0.y, ex * t0.z, ex * t0.w);
    red_add_v4(dst +  4, ex * t1.x, ex * t1.y, ex * t1.z, ex * t1.w);
    red_add_v4(dst +  8, ex * t2.x, ex * t2.y, ex * t2.z, ex * t2.w);
    red_add_v4(dst + 12, ex * t3.x, ex * t3.y, ex * t3.z, ex * t3.w);
    if (l4 == 0) atomicAdd(&g_sum[hi], ex);
}

// ---- x = h + agg/(sum+eps); out_cols = leaky(x @ W.T). 64x64 tile, 4x4/thread.
// Also re-zeros g_agg/g_sum for the next layer when clear!=0.
__global__ void __launch_bounds__(256) k_linear(
        const float* __restrict__ h, int h_stride,
        const float* __restrict__ W,
        float* __restrict__ out,
        int N, int out_stride, int col_off, int clear) {
    __shared__ float Wsh[D][68];       // Wsh[k][j] = W[j*64 + k]
    __shared__ float xs[64][68];

    for (int idx = threadIdx.x; idx < D * D; idx += blockDim.x) {
        int jj = idx >> 6, kk = idx & 63;
        Wsh[kk][jj] = W[idx];
    }

    int nb = blockIdx.x * 64;

    // cooperative load: 64 nodes x 64 floats. thread t: node nb + (t>>2),
    // float4 quads at cols (t&3)*16 + {0,4,8,12}
    {
        int node = nb + (threadIdx.x >> 2);
        int q = (threadIdx.x & 3) * 16;
        if (node < N) {
            float inv = 1.0f / (g_sum[node] + 1e-10f);
            const float* hrow = h + (size_t)node * h_stride;
            float* arow = g_agg + (size_t)node * D;
            float* xrow = xs[threadIdx.x >> 2];
#pragma unroll
            for (int u = 0; u < 4; u++) {
                int f = q + u * 4;
                float4 hv = *(const float4*)(hrow + f);
                float4 av = *(const float4*)(arow + f);
                xrow[f + 0] = hv.x + av.x * inv;
                xrow[f + 1] = hv.y + av.y * inv;
                xrow[f + 2] = hv.z + av.z * inv;
                xrow[f + 3] = hv.w + av.w * inv;
                if (clear) {
                    float4 z = {0.f, 0.f, 0.f, 0.f};
                    *(float4*)(arow + f) = z;
                }
            }
        }
    }
    __syncthreads();

    if (clear) {
        int node = nb + (threadIdx.x >> 2);
        if ((threadIdx.x & 3) == 0 && node < N) g_sum[node] = 0.0f;
    }

    int r = threadIdx.x >> 4;           // node group 0..15 (nodes 4r..4r+3)
    int c4 = (threadIdx.x & 15) * 4;    // output col group

    float4 acc[4];
#pragma unroll
    for (int i = 0; i < 4; i++) acc[i] = make_float4(0.f, 0.f, 0.f, 0.f);

#pragma unroll
    for (int kk = 0; kk < D; kk += 4) {
        float4 wv0 = *(const float4*)&Wsh[kk + 0][c4];
        float4 wv1 = *(const float4*)&Wsh[kk + 1][c4];
        float4 wv2 = *(const float4*)&Wsh[kk + 2][c4];
        float4 wv3 = *(const float4*)&Wsh[kk + 3][c4];
#pragma unroll
        for (int i = 0; i < 4; i++) {
            float4 xv = *(const float4*)&xs[r * 4 + i][kk];
            acc[i].x = fmaf(xv.x, wv0.x, acc[i].x);
            acc[i].y = fmaf(xv.x, wv0.y, acc[i].y);
            acc[i].z = fmaf(xv.x, wv0.z, acc[i].z);
            acc[i].w = fmaf(xv.x, wv0.w, acc[i].w);
            acc[i].x = fmaf(xv.y, wv1.x, acc[i].x);
            acc[i].y = fmaf(xv.y, wv1.y, acc[i].y);
            acc[i].z = fmaf(xv.y, wv1.z, acc[i].z);
            acc[i].w = fmaf(xv.y, wv1.w, acc[i].w);
            acc[i].x = fmaf(xv.z, wv2.x, acc[i].x);
            acc[i].y = fmaf(xv.z, wv2.y, acc[i].y);
            acc[i].z = fmaf(xv.z, wv2.z, acc[i].z);
            acc[i].w = fmaf(xv.z, wv2.w, acc[i].w);
            acc[i].x = fmaf(xv.w, wv3.x, acc[i].x);
            acc[i].y = fmaf(xv.w, wv3.y, acc[i].y);
            acc[i].z = fmaf(xv.w, wv3.z, acc[i].z);
            acc[i].w = fmaf(xv.w, wv3.w, acc[i].w);
        }
    }

#pragma unroll
    for (int i = 0; i < 4; i++) {
        int n = nb + r * 4 + i;
        if (n < N) {
            float4 v = acc[i];
            v.x = v.x > 0.f ? v.x : 0.2f * v.x;
            v.y = v.y > 0.f ? v.y : 0.2f * v.y;
            v.z = v.z > 0.f ? v.z : 0.2f * v.z;
            v.w = v.w > 0.f ? v.w : 0.2f * v.w;
            *(float4*)(out + (size_t)n * out_stride + col_off + c4) = v;
        }
    }
}

extern "C" void kernel_launch(void* const* d_in, const int* in_sizes, int n_in,
                              void* d_out, int out_size) {
    const int*   heads      = (const int*)d_in[0];
    const int*   rels       = (const int*)d_in[1];
    const int*   tails      = (const int*)d_in[2];
    const float* ent        = (const float*)d_in[3];
    const float* rel_embeds = (const float*)d_in[4];
    const float* Ws         = (const float*)d_in[5];
    float*       out        = (float*)d_out;

    int E = in_sizes[0];
    int N = in_sizes[3] / D;
    int L = in_sizes[5] / (D * D);
    int NREL = (L > 0) ? in_sizes[4] / (L * D) : 0;
    int out_stride = D * (L + 1);

    k_copy0<<<(N * (D / 4) + 255) / 256, 256>>>(ent, out, N, out_stride);
    k_init<<<1024, 256>>>(N * D / 4, N);

    int eblocks = (E * 4 + 255) / 256;
    int lblocks = (N + 63) / 64;

    const float* hcur = ent;
    int hstride = D;

    for (int l = 0; l < L; l++) {
        k_edge<<<eblocks, 256>>>(hcur, hstride,
                                 rel_embeds + (size_t)l * NREL * D,
                                 heads, rels, tails, E);
        k_linear<<<lblocks, 256>>>(hcur, hstride, Ws + (size_t)l * D * D, out,
                                   N, out_stride, (l + 1) * D,
                                   (l < L - 1) ? 1 : 0);
        hcur = out + (size_t)(l + 1) * D;   // next layer reads from output slab
        hstride = out_stride;
    }
}

// round 4
// speedup vs baseline: 3.8564x; 1.3396x over previous
#include <cuda_runtime.h>
#include <math.h>

#define D 64
#define MAX_E 1000000
#define MAX_N 100000
#define SCAN_CHUNK 1024
#define MAX_SB ((MAX_N + SCAN_CHUNK - 1) / SCAN_CHUNK)

// ---- device scratch (no allocations allowed) ----
__device__ __align__(16) float g_x[MAX_N * D];   // x = h + agg/(sum+eps), per layer
__device__ int g_cnt[MAX_N];                     // head degree histogram
__device__ int g_off[MAX_N + 1];                 // CSR offsets (exclusive scan)
__device__ int g_cur[MAX_N];                     // scatter cursors
__device__ int g_bsum[MAX_SB + 1];               // scan block sums
__device__ int g_stails[MAX_E];                  // edge tails sorted by head
__device__ int g_srels[MAX_E];                   // edge rels  sorted by head

__device__ __forceinline__ float tanh_fast(float x) {
    float t, r;
    asm("ex2.approx.f32 %0, %1;" : "=f"(t) : "f"(x * 2.885390081777927f));
    asm("rcp.approx.f32 %0, %1;" : "=f"(r) : "f"(t + 1.0f));
    return (t - 1.0f) * r;
}

__device__ __forceinline__ float exp_fast(float x) {
    float t;
    asm("ex2.approx.f32 %0, %1;" : "=f"(t) : "f"(x * 1.4426950408889634f));
    return t;
}

// =================== CSR build (counting sort by head) ===================

__global__ void k_zero_cnt(int n) {
    int i = blockIdx.x * blockDim.x + threadIdx.x;
    if (i < n) g_cnt[i] = 0;
}

__global__ void k_hist(const int* __restrict__ heads, int E) {
    int i = blockIdx.x * blockDim.x + threadIdx.x;
    if (i < E) atomicAdd(&g_cnt[heads[i]], 1);
}

// per-1024-chunk exclusive scan; chunk total -> g_bsum[b]
__global__ void k_scan1(int n) {
    __shared__ int wsum[8];
    int base = blockIdx.x * SCAN_CHUNK;
    int t = threadIdx.x;
    int idx = base + t * 4;
    int c0 = (idx + 0 < n) ? g_cnt[idx + 0] : 0;
    int c1 = (idx + 1 < n) ? g_cnt[idx + 1] : 0;
    int c2 = (idx + 2 < n) ? g_cnt[idx + 2] : 0;
    int c3 = (idx + 3 < n) ? g_cnt[idx + 3] : 0;
    int s = c0 + c1 + c2 + c3;
    int lane = t & 31, w = t >> 5;
    int ps = s;
#pragma unroll
    for (int o = 1; o < 32; o <<= 1) {
        int v = __shfl_up_sync(0xffffffffu, ps, o);
        if (lane >= o) ps += v;
    }
    if (lane == 31) wsum[w] = ps;
    __syncthreads();
    if (t == 0) {
        int a = 0;
#pragma unroll
        for (int i = 0; i < 8; i++) { int v = wsum[i]; wsum[i] = a; a += v; }
        g_bsum[blockIdx.x] = a;
    }
    __syncthreads();
    int excl = wsum[w] + ps - s;     // exclusive prefix of this thread's first elem
    if (idx + 0 < n) g_off[idx + 0] = excl;
    if (idx + 1 < n) g_off[idx + 1] = excl + c0;
    if (idx + 2 < n) g_off[idx + 2] = excl + c0 + c1;
    if (idx + 3 < n) g_off[idx + 3] = excl + c0 + c1 + c2;
}

// scan the (<=98) block sums sequentially
__global__ void k_scan2(int nb) {
    if (threadIdx.x == 0 && blockIdx.x == 0) {
        int run = 0;
        for (int b = 0; b < nb; b++) { int v = g_bsum[b]; g_bsum[b] = run; run += v; }
        g_bsum[nb] = run;
    }
}

// add block offsets, produce final g_off + cursors; g_off[n] = E
__global__ void k_scan3(int n, int E) {
    int b = blockIdx.x;
    int add = g_bsum[b];
    int idx = b * SCAN_CHUNK + threadIdx.x * 4;
#pragma unroll
    for (int u = 0; u < 4; u++) {
        int i = idx + u;
        if (i < n) {
            int v = g_off[i] + add;
            g_off[i] = v;
            g_cur[i] = v;
        }
    }
    if (b == 0 && threadIdx.x == 0) g_off[n] = E;
}

__global__ void k_scatter(const int* __restrict__ heads,
                          const int* __restrict__ rels,
                          const int* __restrict__ tails, int E) {
    int i = blockIdx.x * blockDim.x + threadIdx.x;
    if (i >= E) return;
    int pos = atomicAdd(&g_cur[heads[i]], 1);
    g_stails[pos] = tails[i];
    g_srels[pos]  = rels[i];
}

// =================== misc ===================

__global__ void k_copy0(const float* __restrict__ ent, float* __restrict__ out,
                        int N, int out_stride) {
    int i = blockIdx.x * blockDim.x + threadIdx.x;
    int total = N * (D / 4);
    if (i < total) {
        int n = i >> 4, f = i & 15;
        float4 v = ((const float4*)ent)[i];
        *(float4*)(out + (size_t)n * out_stride + f * 4) = v;
    }
}

// =================== edge pass: one warp per head, CSR, no atomics =========
// Computes x[head] = e_h + (Σ exp(s_e) e_t) / (Σ exp(s_e) + eps), plain store.
__global__ void __launch_bounds__(256) k_edge_csr(
        const float* __restrict__ h, int h_stride,
        const float* __restrict__ rel_emb, int N) {
    int gw = (blockIdx.x * 256 + threadIdx.x) >> 5;
    if (gw >= N) return;
    int lane = threadIdx.x & 31;
    int beg = g_off[gw], end = g_off[gw + 1];

    float2 eh = *(const float2*)(h + (size_t)gw * h_stride + lane * 2);
    float ax = 0.f, ay = 0.f, ssum = 0.f;

    int i = beg;
    for (; i + 2 <= end; i += 2) {
        int t0 = g_stails[i],     r0 = g_srels[i];
        int t1 = g_stails[i + 1], r1 = g_srels[i + 1];
        float2 et0 = *(const float2*)(h + (size_t)t0 * h_stride + lane * 2);
        float2 er0 = *(const float2*)(rel_emb + r0 * D + lane * 2);
        float2 et1 = *(const float2*)(h + (size_t)t1 * h_stride + lane * 2);
        float2 er1 = *(const float2*)(rel_emb + r1 * D + lane * 2);
        float s0 = et0.x * tanh_fast(eh.x + er0.x) + et0.y * tanh_fast(eh.y + er0.y);
        float s1 = et1.x * tanh_fast(eh.x + er1.x) + et1.y * tanh_fast(eh.y + er1.y);
#pragma unroll
        for (int o = 16; o; o >>= 1) {
            s0 += __shfl_xor_sync(0xffffffffu, s0, o);
            s1 += __shfl_xor_sync(0xffffffffu, s1, o);
        }
        float ex0 = exp_fast(s0), ex1 = exp_fast(s1);
        ax += ex0 * et0.x + ex1 * et1.x;
        ay += ex0 * et0.y + ex1 * et1.y;
        ssum += ex0 + ex1;
    }
    if (i < end) {
        int t0 = g_stails[i], r0 = g_srels[i];
        float2 et0 = *(const float2*)(h + (size_t)t0 * h_stride + lane * 2);
        float2 er0 = *(const float2*)(rel_emb + r0 * D + lane * 2);
        float s0 = et0.x * tanh_fast(eh.x + er0.x) + et0.y * tanh_fast(eh.y + er0.y);
#pragma unroll
        for (int o = 16; o; o >>= 1)
            s0 += __shfl_xor_sync(0xffffffffu, s0, o);
        float ex0 = exp_fast(s0);
        ax += ex0 * et0.x;
        ay += ex0 * et0.y;
        ssum += ex0;
    }

    float inv = 1.0f / (ssum + 1e-10f);
    float2 x = { eh.x + ax * inv, eh.y + ay * inv };
    *(float2*)(g_x + (size_t)gw * D + lane * 2) = x;
}

// =================== linear: out_cols = leaky(x @ W.T), 64x64 tile =========
__global__ void __launch_bounds__(256) k_linear(
        const float* __restrict__ W,
        float* __restrict__ out,
        int N, int out_stride, int col_off) {
    __shared__ float Wsh[D][68];       // Wsh[k][j] = W[j*64 + k]
    __shared__ float xs[64][68];

    for (int idx = threadIdx.x; idx < D * D; idx += blockDim.x) {
        int jj = idx >> 6, kk = idx & 63;
        Wsh[kk][jj] = W[idx];
    }

    int nb = blockIdx.x * 64;
    {
        int node = nb + (threadIdx.x >> 2);
        int q = (threadIdx.x & 3) * 16;
        if (node < N) {
            const float* xr = g_x + (size_t)node * D;
            float* row = xs[threadIdx.x >> 2];
#pragma unroll
            for (int u = 0; u < 4; u++) {
                int f = q + u * 4;
                *(float4*)(row + f) = *(const float4*)(xr + f);
            }
        }
    }
    __syncthreads();

    int r = threadIdx.x >> 4;           // node group 0..15
    int c4 = (threadIdx.x & 15) * 4;    // output col group

    float4 acc[4];
#pragma unroll
    for (int i = 0; i < 4; i++) acc[i] = make_float4(0.f, 0.f, 0.f, 0.f);

#pragma unroll
    for (int kk = 0; kk < D; kk += 4) {
        float4 wv0 = *(const float4*)&Wsh[kk + 0][c4];
        float4 wv1 = *(const float4*)&Wsh[kk + 1][c4];
        float4 wv2 = *(const float4*)&Wsh[kk + 2][c4];
        float4 wv3 = *(const float4*)&Wsh[kk + 3][c4];
#pragma unroll
        for (int i = 0; i < 4; i++) {
            float4 xv = *(const float4*)&xs[r * 4 + i][kk];
            acc[i].x = fmaf(xv.x, wv0.x, acc[i].x);
            acc[i].y = fmaf(xv.x, wv0.y, acc[i].y);
            acc[i].z = fmaf(xv.x, wv0.z, acc[i].z);
            acc[i].w = fmaf(xv.x, wv0.w, acc[i].w);
            acc[i].x = fmaf(xv.y, wv1.x, acc[i].x);
            acc[i].y = fmaf(xv.y, wv1.y, acc[i].y);
            acc[i].z = fmaf(xv.y, wv1.z, acc[i].z);
            acc[i].w = fmaf(xv.y, wv1.w, acc[i].w);
            acc[i].x = fmaf(xv.z, wv2.x, acc[i].x);
            acc[i].y = fmaf(xv.z, wv2.y, acc[i].y);
            acc[i].z = fmaf(xv.z, wv2.z, acc[i].z);
            acc[i].w = fmaf(xv.z, wv2.w, acc[i].w);
            acc[i].x = fmaf(xv.w, wv3.x, acc[i].x);
            acc[i].y = fmaf(xv.w, wv3.y, acc[i].y);
            acc[i].z = fmaf(xv.w, wv3.z, acc[i].z);
            acc[i].w = fmaf(xv.w, wv3.w, acc[i].w);
        }
    }

#pragma unroll
    for (int i = 0; i < 4; i++) {
        int n = nb + r * 4 + i;
        if (n < N) {
            float4 v = acc[i];
            v.x = v.x > 0.f ? v.x : 0.2f * v.x;
            v.y = v.y > 0.f ? v.y : 0.2f * v.y;
            v.z = v.z > 0.f ? v.z : 0.2f * v.z;
            v.w = v.w > 0.f ? v.w : 0.2f * v.w;
            *(float4*)(out + (size_t)n * out_stride + col_off + c4) = v;
        }
    }
}

extern "C" void kernel_launch(void* const* d_in, const int* in_sizes, int n_in,
                              void* d_out, int out_size) {
    const int*   heads      = (const int*)d_in[0];
    const int*   rels       = (const int*)d_in[1];
    const int*   tails      = (const int*)d_in[2];
    const float* ent        = (const float*)d_in[3];
    const float* rel_embeds = (const float*)d_in[4];
    const float* Ws         = (const float*)d_in[5];
    float*       out        = (float*)d_out;

    int E = in_sizes[0];
    int N = in_sizes[3] / D;
    int L = in_sizes[5] / (D * D);
    int NREL = (L > 0) ? in_sizes[4] / (L * D) : 0;
    int out_stride = D * (L + 1);
    int SB = (N + SCAN_CHUNK - 1) / SCAN_CHUNK;

    // --- CSR build (once per call) ---
    k_zero_cnt<<<(N + 255) / 256, 256>>>(N);
    k_hist<<<(E + 255) / 256, 256>>>(heads, E);
    k_scan1<<<SB, 256>>>(N);
    k_scan2<<<1, 32>>>(SB);
    k_scan3<<<SB, 256>>>(N, E);
    k_scatter<<<(E + 255) / 256, 256>>>(heads, rels, tails, E);

    // layer-0 output columns
    k_copy0<<<(N * (D / 4) + 255) / 256, 256>>>(ent, out, N, out_stride);

    int eblocks = (N * 32 + 255) / 256;       // warp per head
    int lblocks = (N + 63) / 64;

    const float* hcur = ent;
    int hstride = D;

    for (int l = 0; l < L; l++) {
        k_edge_csr<<<eblocks, 256>>>(hcur, hstride,
                                     rel_embeds + (size_t)l * NREL * D, N);
        k_linear<<<lblocks, 256>>>(Ws + (size_t)l * D * D, out,
                                   N, out_stride, (l + 1) * D);
        hcur = out + (size_t)(l + 1) * D;
        hstride = out_stride;
    }
}